// round 16
// baseline (speedup 1.0000x reference)
#include <cuda_runtime.h>
#include <cstdint>

#define BB 1024
#define SS 128
#define HH 1024
#define CC 10
#define NCTA 128

// ---------------- scratch (allocation-free) ----------------
// hidden state as 2-level int8 fixed point: h ~= a1*2^-7 + a2*2^-14
__device__ __align__(16) signed char g_ha1[2][BB * HH];
__device__ __align__(16) signed char g_ha2[2][BB * HH];
// per-(M-group, warp-group) slice counters, lo/hi producer halves, 128B apart
__device__ unsigned g_barw[8 * 4 * 2 * 32];

#define SC_P 3.814697265625e-06f      // 2^-18
#define SC_Q 2.9802322387695312e-08f  // 2^-25

// ---------------- helpers ----------------
__device__ __forceinline__ uint32_t smem_u32(const void* p) {
    uint32_t a;
    asm("{ .reg .u64 t; cvta.to.shared.u64 t, %1; cvt.u32.u64 %0, t; }" : "=r"(a) : "l"(p));
    return a;
}
#define CP_ASYNC16(dst, src) \
    asm volatile("cp.async.cg.shared.global [%0], [%1], 16;" :: "r"(dst), "l"(src) : "memory")
#define CP_COMMIT() asm volatile("cp.async.commit_group;" ::: "memory")
#define CP_WAIT(n)  asm volatile("cp.async.wait_group %0;" :: "n"(n) : "memory")
#define GBAR64(id)  asm volatile("bar.sync %0, 64;" :: "r"(id) : "memory")

#define LDSM4(r0, r1, r2, r3, addr) \
    asm volatile("ldmatrix.sync.aligned.m8n8.x4.shared.b16 {%0,%1,%2,%3}, [%4];" \
        : "=r"(r0), "=r"(r1), "=r"(r2), "=r"(r3) : "r"(addr))

__device__ __forceinline__ void mma_s8(int* d, const uint32_t* a, const uint32_t* b) {
    asm volatile(
        "mma.sync.aligned.m16n8k32.row.col.s32.s8.s8.s32 "
        "{%0,%1,%2,%3}, {%4,%5,%6,%7}, {%8,%9}, {%0,%1,%2,%3};\n"
        : "+r"(d[0]), "+r"(d[1]), "+r"(d[2]), "+r"(d[3])
        : "r"(a[0]), "r"(a[1]), "r"(a[2]), "r"(a[3]), "r"(b[0]), "r"(b[1]));
}

// tanh(z) = 1 - 2/(e^{2z}+1): no clamps needed (inf/0 limits give +-1 exactly)
__device__ __forceinline__ float fast_tanh(float z) {
    float e = __expf(2.f * z);
    return 1.f - __fdividef(2.f, e + 1.f);
}

__device__ __forceinline__ int clamp127(float v) {
    return max(-127, min(127, __float2int_rn(v)));
}

// ---------------- SMEM layout (bytes) ----------------
#define B_PLANE   65536
#define A_BASE    131072
#define A_STAGE   32768
#define A_PLANE   16384
#define SMEM_TOTAL 229376

// ---------------- persistent RNN kernel ----------------
// 128 CTAs x 256 threads (8 warps: 4 wm x 2 wn), warp tile 32x32.
// Prologue quantizes whh rows directly into resident SMEM B planes (no prep
// kernel, no global W scratch). t=0 skips the GEMM entirely (h0 == 0).
// Sync: (mg, wm) slice counters, R12-proven primitive; proj resets counters.
__global__ void __launch_bounds__(256, 1) rnn_persist(
    const float* __restrict__ x, const float* __restrict__ whx,
    const float* __restrict__ bh, const float* __restrict__ whh)
{
    extern __shared__ char smem[];
    __shared__ float whx_s[64], bh_s[64];
    const uint32_t sb = smem_u32(smem);

    const int tid  = threadIdx.x;
    const int warp = tid >> 5;
    const int lane = tid & 31;
    const int gid  = lane >> 2;
    const int tig  = lane & 3;
    const int wm   = warp & 3;
    const int wn   = warp >> 2;        // 0..1
    const int li   = wn * 32 + lane;   // 0..63 within wm-slice

    const int mg = blockIdx.x >> 4;    // M-group 0..7
    const int ng = blockIdx.x & 15;    // N-block 0..15
    const int M0 = mg * 128;
    const int N0 = ng * 64;
    unsigned* const ctr_lo  = &g_barw[((mg * 4 + wm) * 2 + 0) * 32];
    unsigned* const ctr_hi  = &g_barw[((mg * 4 + wm) * 2 + 1) * 32];
    unsigned* const ctr_pub = &g_barw[((mg * 4 + wm) * 2 + (ng >> 3)) * 32];

    if (tid < 64) { whx_s[tid] = whx[N0 + tid]; bh_s[tid] = bh[N0 + tid]; }

    // ---- prologue: quantize whh rows N0..N0+63 straight into resident SMEM
    //      B planes (b1 @2^-11, b2 @2^-18), XOR-swizzled 16B granules ----
    for (int g = tid; g < 64 * 256; g += 256) {    // 4-col groups
        const int r  = g >> 8;
        const int c  = (g & 255) * 4;
        const float4 w4 = *(const float4*)(whh + (N0 + r) * HH + c);
        int b1x = clamp127(w4.x * 2048.f);
        int b1y = clamp127(w4.y * 2048.f);
        int b1z = clamp127(w4.z * 2048.f);
        int b1w = clamp127(w4.w * 2048.f);
        int b2x = clamp127((w4.x - (float)b1x * 4.8828125e-4f) * 262144.f);
        int b2y = clamp127((w4.y - (float)b1y * 4.8828125e-4f) * 262144.f);
        int b2z = clamp127((w4.z - (float)b1z * 4.8828125e-4f) * 262144.f);
        int b2w = clamp127((w4.w - (float)b1w * 4.8828125e-4f) * 262144.f);
        uint32_t p1 = (b1x & 0xFF) | ((b1y & 0xFF) << 8) |
                      ((b1z & 0xFF) << 16) | ((uint32_t)(b1w & 0xFF) << 24);
        uint32_t p2 = (b2x & 0xFF) | ((b2y & 0xFF) << 8) |
                      ((b2z & 0xFF) << 16) | ((uint32_t)(b2w & 0xFF) << 24);
        const int c16 = c >> 4, off = c & 15;
        const uint32_t dst = r * 1024 + (((uint32_t)(c16 ^ (r & 7))) << 4) + off;
        *(uint32_t*)(smem + dst) = p1;
        *(uint32_t*)(smem + dst + B_PLANE) = p2;
    }
    __syncthreads();

    // ---- per-lane ldmatrix address components ----
    const int a_row = wm * 32 + (lane & 7) + ((lane >> 3) & 1) * 8;
    const int ka    = (lane >> 4) & 1;
    const int arx   = a_row & 7;
    const int b_row = wn * 32 + (lane & 7) + ((lane >> 4) & 1) * 8;
    const int kb    = (lane >> 3) & 1;
    const int brx   = b_row & 7;
    const uint32_t bbase = sb + b_row * 1024;
    const int brx2  = (b_row + 16) & 7;
    const uint32_t bbase2 = sb + (b_row + 16) * 1024;
    const int n_ep = N0 + wn * 32 + 2 * tig;
    const int r_ep = M0 + wm * 32 + gid;

    for (int t = 0; t < SS; ++t) {
        const signed char* __restrict__ ha1 = g_ha1[t & 1];
        const signed char* __restrict__ ha2 = g_ha2[t & 1];

        const float x00 = x[r_ep * SS + t];
        const float x01 = x[(r_ep + 8) * SS + t];
        const float x10 = x[(r_ep + 16) * SS + t];
        const float x11 = x[(r_ep + 24) * SS + t];

        int accP[2][4][4], accQ[2][4][4], accR[2][4][4];
        #pragma unroll
        for (int a = 0; a < 2; a++)
            #pragma unroll
            for (int b = 0; b < 4; b++)
                #pragma unroll
                for (int c = 0; c < 4; c++) {
                    accP[a][b][c] = 0; accQ[a][b][c] = 0; accR[a][b][c] = 0;
                }

        // slice-local fill: this wm-slice's 32 A rows, both planes (512 x 16B, 64 thr)
        auto fillg = [&](int c) {
            const uint32_t stb = sb + A_BASE + (c % 3) * A_STAGE;
            const int k0 = c * 128;
            #pragma unroll
            for (int i = 0; i < 8; ++i) {
                int gg = li + i * 64;             // 0..511
                int plane = gg >> 8, r32 = (gg >> 3) & 31, c16 = gg & 7;
                int r = wm * 32 + r32;
                const signed char* a = plane ? ha2 : ha1;
                const char* src = (const char*)(a + (M0 + r) * HH + k0) + c16 * 16;
                uint32_t dst = stb + plane * A_PLANE + r * 128 +
                               (((uint32_t)(c16 ^ (r & 7))) << 4);
                CP_ASYNC16(dst, src);
            }
            CP_COMMIT();
        };

        if (t > 0) {   // t = 0: h is all-zero -> GEMM contributes exactly 0; skip it
            if (warp == wm && lane == 0) {
                const unsigned target = 8u * t;
                unsigned v;
                do {
                    asm volatile("ld.acquire.gpu.global.u32 %0, [%1];" : "=r"(v) : "l"(ctr_lo));
                } while (v < target);
            }
            GBAR64(1 + wm);
            fillg(0); fillg(1);
            if (warp == wm && lane == 0) {
                const unsigned target = 8u * t;
                unsigned v;
                do {
                    asm volatile("ld.acquire.gpu.global.u32 %0, [%1];" : "=r"(v) : "l"(ctr_hi));
                } while (v < target);
            }
            GBAR64(1 + wm);

            // fragment double-buffer
            uint32_t A1f[2][2][4], A2f[2][2][4];   // [buf][mi][4]
            uint32_t B1f[2][4][2], B2f[2][4][2];   // [buf][ni][2]

            auto load_frags = [&](int buf, uint32_t stb, int c, int ks) {
                const uint32_t acol = ((uint32_t)((ks * 2 + ka) ^ arx)) << 4;
                #pragma unroll
                for (int mi = 0; mi < 2; ++mi) {
                    uint32_t ad = stb + (a_row + mi * 16) * 128 + acol;
                    LDSM4(A1f[buf][mi][0], A1f[buf][mi][1], A1f[buf][mi][2], A1f[buf][mi][3], ad);
                    LDSM4(A2f[buf][mi][0], A2f[buf][mi][1], A2f[buf][mi][2], A2f[buf][mi][3], ad + A_PLANE);
                }
                {
                    uint32_t bd = bbase + c * 128 + (((uint32_t)((ks * 2 + kb) ^ brx)) << 4);
                    LDSM4(B1f[buf][0][0], B1f[buf][0][1], B1f[buf][1][0], B1f[buf][1][1], bd);
                    LDSM4(B2f[buf][0][0], B2f[buf][0][1], B2f[buf][1][0], B2f[buf][1][1], bd + B_PLANE);
                    uint32_t bd2 = bbase2 + c * 128 + (((uint32_t)((ks * 2 + kb) ^ brx2)) << 4);
                    LDSM4(B1f[buf][2][0], B1f[buf][2][1], B1f[buf][3][0], B1f[buf][3][1], bd2);
                    LDSM4(B2f[buf][2][0], B2f[buf][2][1], B2f[buf][3][0], B2f[buf][3][1], bd2 + B_PLANE);
                }
            };
            auto issue_mma = [&](int buf) {
                #pragma unroll
                for (int mi = 0; mi < 2; ++mi)
                    #pragma unroll
                    for (int ni = 0; ni < 4; ++ni) {
                        mma_s8(accP[mi][ni], A1f[buf][mi], B1f[buf][ni]);
                        mma_s8(accQ[mi][ni], A2f[buf][mi], B1f[buf][ni]);
                        mma_s8(accR[mi][ni], A1f[buf][mi], B2f[buf][ni]);
                    }
            };

            #pragma unroll
            for (int c = 0; c < 8; ++c) {
                if (c < 7) { CP_WAIT(1); } else { CP_WAIT(0); }
                GBAR64(1 + wm);               // slice convergence: chunk-c data landed
                if (c + 2 < 8) fillg(c + 2);

                const uint32_t stb = sb + A_BASE + (c % 3) * A_STAGE;
                load_frags(0, stb, c, 0);
                #pragma unroll
                for (int ks = 0; ks < 4; ++ks) {
                    if (ks < 3) load_frags((ks + 1) & 1, stb, c, ks + 1);
                    issue_mma(ks & 1);
                }
            }
        }

        // epilogue: v = accP*2^-18 + (accQ+accR)*2^-25 + x*whx + bh; tanh; re-split
        signed char* __restrict__ o1 = g_ha1[(t + 1) & 1];
        signed char* __restrict__ o2 = g_ha2[(t + 1) & 1];
        #pragma unroll
        for (int mi = 0; mi < 2; ++mi) {
            const int r0 = r_ep + mi * 16;
            const float x0 = mi ? x10 : x00;
            const float x1 = mi ? x11 : x01;
            #pragma unroll
            for (int ni = 0; ni < 4; ++ni) {
                const int n0 = n_ep + ni * 8;
                const int ns = wn * 32 + 2 * tig + ni * 8;
                const float w0 = whx_s[ns], w1 = whx_s[ns + 1];
                const float b0 = bh_s[ns],  b1 = bh_s[ns + 1];
                float v00 = fast_tanh((float)accP[mi][ni][0] * SC_P + (float)(accQ[mi][ni][0] + accR[mi][ni][0]) * SC_Q + x0 * w0 + b0);
                float v01 = fast_tanh((float)accP[mi][ni][1] * SC_P + (float)(accQ[mi][ni][1] + accR[mi][ni][1]) * SC_Q + x0 * w1 + b1);
                float v10 = fast_tanh((float)accP[mi][ni][2] * SC_P + (float)(accQ[mi][ni][2] + accR[mi][ni][2]) * SC_Q + x1 * w0 + b0);
                float v11 = fast_tanh((float)accP[mi][ni][3] * SC_P + (float)(accQ[mi][ni][3] + accR[mi][ni][3]) * SC_Q + x1 * w1 + b1);
                int p00 = clamp127(v00 * 128.f), p01 = clamp127(v01 * 128.f);
                int p10 = clamp127(v10 * 128.f), p11 = clamp127(v11 * 128.f);
                int q00 = clamp127((v00 - (float)p00 * 0.0078125f) * 16384.f);
                int q01 = clamp127((v01 - (float)p01 * 0.0078125f) * 16384.f);
                int q10 = clamp127((v10 - (float)p10 * 0.0078125f) * 16384.f);
                int q11 = clamp127((v11 - (float)p11 * 0.0078125f) * 16384.f);
                *(uint16_t*)(o1 + r0 * HH + n0) = (uint16_t)((p00 & 0xFF) | ((p01 & 0xFF) << 8));
                *(uint16_t*)(o2 + r0 * HH + n0) = (uint16_t)((q00 & 0xFF) | ((q01 & 0xFF) << 8));
                *(uint16_t*)(o1 + (r0 + 8) * HH + n0) = (uint16_t)((p10 & 0xFF) | ((p11 & 0xFF) << 8));
                *(uint16_t*)(o2 + (r0 + 8) * HH + n0) = (uint16_t)((q10 & 0xFF) | ((q11 & 0xFF) << 8));
            }
        }

        // publish: slice stores visible (named bar), then release our half-counter
        if (t + 1 < SS) {
            GBAR64(1 + wm);
            if (warp == wm && lane == 0) {
                __threadfence();
                atomicAdd(ctr_pub, 1u);
            }
        }
    }
}

// ---------------- output projection (+ counter reset for graph replays) ----------------
__global__ void proj_kernel(const float* __restrict__ wph,
                            const float* __restrict__ bp,
                            float* __restrict__ out) {
    __shared__ float red[CC][128];
    int b = blockIdx.x, tid = threadIdx.x;
    // reset slice counters so the NEXT kernel_launch call (graph replay)
    // starts from 0; runs after rnn_persist by stream order.
    if (b == 0) {
        for (int i = tid; i < 8 * 4 * 2 * 32; i += 128) g_barw[i] = 0u;
    }
    float acc[CC];
    #pragma unroll
    for (int c = 0; c < CC; ++c) acc[c] = 0.f;
    for (int k = tid; k < HH; k += 128) {
        float hv = (float)g_ha1[0][b * HH + k] * 0.0078125f
                 + (float)g_ha2[0][b * HH + k] * 6.103515625e-5f;
        #pragma unroll
        for (int c = 0; c < CC; ++c) acc[c] += hv * wph[c * HH + k];
    }
    #pragma unroll
    for (int c = 0; c < CC; ++c) red[c][tid] = acc[c];
    __syncthreads();
    for (int off = 64; off > 0; off >>= 1) {
        if (tid < off) {
            #pragma unroll
            for (int c = 0; c < CC; ++c) red[c][tid] += red[c][tid + off];
        }
        __syncthreads();
    }
    if (tid < CC) out[b * CC + tid] = red[tid][0] + bp[tid];
}

extern "C" void kernel_launch(void* const* d_in, const int* in_sizes, int n_in,
                              void* d_out, int out_size) {
    const float* x   = (const float*)d_in[0];
    const float* whx = (const float*)d_in[1];
    const float* whh = (const float*)d_in[2];
    const float* bh  = (const float*)d_in[3];
    const float* wph = (const float*)d_in[4];
    const float* bp  = (const float*)d_in[5];
    float* out = (float*)d_out;

    cudaFuncSetAttribute(rnn_persist,
                         cudaFuncAttributeMaxDynamicSharedMemorySize, SMEM_TOTAL);

    rnn_persist<<<NCTA, 256, SMEM_TOTAL>>>(x, whx, bh, whh);
    proj_kernel<<<BB, 128>>>(wph, bp, out);
}

// round 17
// speedup vs baseline: 1.0285x; 1.0285x over previous
#include <cuda_runtime.h>
#include <cstdint>

#define BB 1024
#define SS 128
#define HH 1024
#define CC 10
#define NCTA 128

// ---------------- scratch (allocation-free) ----------------
// hidden state as 2-level int8 fixed point: h ~= a1*2^-7 + a2*2^-14
__device__ __align__(16) signed char g_ha1[2][BB * HH];
__device__ __align__(16) signed char g_ha2[2][BB * HH];
// per-(M-group, warp-group) slice counters, lo/hi producer halves, 128B apart
__device__ unsigned g_barw[8 * 4 * 2 * 32];

#define SC_P 3.814697265625e-06f      // 2^-18
#define SC_Q 2.9802322387695312e-08f  // 2^-25

// ---------------- helpers ----------------
__device__ __forceinline__ uint32_t smem_u32(const void* p) {
    uint32_t a;
    asm("{ .reg .u64 t; cvta.to.shared.u64 t, %1; cvt.u32.u64 %0, t; }" : "=r"(a) : "l"(p));
    return a;
}
#define CP_ASYNC16(dst, src) \
    asm volatile("cp.async.cg.shared.global [%0], [%1], 16;" :: "r"(dst), "l"(src) : "memory")
#define CP_COMMIT() asm volatile("cp.async.commit_group;" ::: "memory")
#define CP_WAIT(n)  asm volatile("cp.async.wait_group %0;" :: "n"(n) : "memory")
#define GBAR64(id)  asm volatile("bar.sync %0, 64;" :: "r"(id) : "memory")

#define LDSM4(r0, r1, r2, r3, addr) \
    asm volatile("ldmatrix.sync.aligned.m8n8.x4.shared.b16 {%0,%1,%2,%3}, [%4];" \
        : "=r"(r0), "=r"(r1), "=r"(r2), "=r"(r3) : "r"(addr))

__device__ __forceinline__ void mma_s8(int* d, const uint32_t* a, const uint32_t* b) {
    asm volatile(
        "mma.sync.aligned.m16n8k32.row.col.s32.s8.s8.s32 "
        "{%0,%1,%2,%3}, {%4,%5,%6,%7}, {%8,%9}, {%0,%1,%2,%3};\n"
        : "+r"(d[0]), "+r"(d[1]), "+r"(d[2]), "+r"(d[3])
        : "r"(a[0]), "r"(a[1]), "r"(a[2]), "r"(a[3]), "r"(b[0]), "r"(b[1]));
}

// tanh(z) = 1 - 2/(e^{2z}+1): no clamps needed (inf/0 limits give +-1 exactly)
__device__ __forceinline__ float fast_tanh(float z) {
    float e = __expf(2.f * z);
    return 1.f - __fdividef(2.f, e + 1.f);
}

__device__ __forceinline__ int clamp127(float v) {
    return max(-127, min(127, __float2int_rn(v)));
}

// ---------------- SMEM layout (bytes) ----------------
#define B_PLANE   65536
#define A_BASE    131072
#define A_STAGE   32768
#define A_PLANE   16384
#define SMEM_TOTAL 229376

// ---------------- persistent RNN kernel ----------------
// 128 CTAs x 256 threads (8 warps: 4 wm x 2 wn), warp tile 32x32.
// Prologue quantizes whh rows directly into resident SMEM B planes. t=0 skips
// the GEMM (h0 == 0). Sync: (mg, wm) slice counters (R12-proven primitive).
// NEW R17: epilogue stages packed outputs in SMEM (80B row stride) and emits
// fully-coalesced 16B global stores instead of 32 scattered 2B stores/thread.
__global__ void __launch_bounds__(256, 1) rnn_persist(
    const float* __restrict__ x, const float* __restrict__ whx,
    const float* __restrict__ bh, const float* __restrict__ whh)
{
    extern __shared__ char smem[];
    __shared__ float whx_s[64], bh_s[64];
    const uint32_t sb = smem_u32(smem);

    const int tid  = threadIdx.x;
    const int warp = tid >> 5;
    const int lane = tid & 31;
    const int gid  = lane >> 2;
    const int tig  = lane & 3;
    const int wm   = warp & 3;
    const int wn   = warp >> 2;        // 0..1
    const int li   = wn * 32 + lane;   // 0..63 within wm-slice

    const int mg = blockIdx.x >> 4;    // M-group 0..7
    const int ng = blockIdx.x & 15;    // N-block 0..15
    const int M0 = mg * 128;
    const int N0 = ng * 64;
    unsigned* const ctr_lo  = &g_barw[((mg * 4 + wm) * 2 + 0) * 32];
    unsigned* const ctr_hi  = &g_barw[((mg * 4 + wm) * 2 + 1) * 32];
    unsigned* const ctr_pub = &g_barw[((mg * 4 + wm) * 2 + (ng >> 3)) * 32];

    if (tid < 64) { whx_s[tid] = whx[N0 + tid]; bh_s[tid] = bh[N0 + tid]; }

    // ---- prologue: quantize whh rows N0..N0+63 straight into resident SMEM
    //      B planes (b1 @2^-11, b2 @2^-18), XOR-swizzled 16B granules ----
    for (int g = tid; g < 64 * 256; g += 256) {    // 4-col groups
        const int r  = g >> 8;
        const int c  = (g & 255) * 4;
        const float4 w4 = *(const float4*)(whh + (N0 + r) * HH + c);
        int b1x = clamp127(w4.x * 2048.f);
        int b1y = clamp127(w4.y * 2048.f);
        int b1z = clamp127(w4.z * 2048.f);
        int b1w = clamp127(w4.w * 2048.f);
        int b2x = clamp127((w4.x - (float)b1x * 4.8828125e-4f) * 262144.f);
        int b2y = clamp127((w4.y - (float)b1y * 4.8828125e-4f) * 262144.f);
        int b2z = clamp127((w4.z - (float)b1z * 4.8828125e-4f) * 262144.f);
        int b2w = clamp127((w4.w - (float)b1w * 4.8828125e-4f) * 262144.f);
        uint32_t p1 = (b1x & 0xFF) | ((b1y & 0xFF) << 8) |
                      ((b1z & 0xFF) << 16) | ((uint32_t)(b1w & 0xFF) << 24);
        uint32_t p2 = (b2x & 0xFF) | ((b2y & 0xFF) << 8) |
                      ((b2z & 0xFF) << 16) | ((uint32_t)(b2w & 0xFF) << 24);
        const int c16 = c >> 4, off = c & 15;
        const uint32_t dst = r * 1024 + (((uint32_t)(c16 ^ (r & 7))) << 4) + off;
        *(uint32_t*)(smem + dst) = p1;
        *(uint32_t*)(smem + dst + B_PLANE) = p2;
    }
    __syncthreads();

    // ---- per-lane ldmatrix address components ----
    const int a_row = wm * 32 + (lane & 7) + ((lane >> 3) & 1) * 8;
    const int ka    = (lane >> 4) & 1;
    const int arx   = a_row & 7;
    const int b_row = wn * 32 + (lane & 7) + ((lane >> 4) & 1) * 8;
    const int kb    = (lane >> 3) & 1;
    const int brx   = b_row & 7;
    const uint32_t bbase = sb + b_row * 1024;
    const int brx2  = (b_row + 16) & 7;
    const uint32_t bbase2 = sb + (b_row + 16) * 1024;
    const int r_ep = M0 + wm * 32 + gid;
    // epilogue staging region: this slice's rows inside stage 0 (idle then).
    // Layout: plane (0/1) at +p*A_PLANE, row stride 80B (16B aligned).
    const int stg_base = A_BASE + wm * 32 * 128;

    for (int t = 0; t < SS; ++t) {
        const signed char* __restrict__ ha1 = g_ha1[t & 1];
        const signed char* __restrict__ ha2 = g_ha2[t & 1];

        const float x00 = x[r_ep * SS + t];
        const float x01 = x[(r_ep + 8) * SS + t];
        const float x10 = x[(r_ep + 16) * SS + t];
        const float x11 = x[(r_ep + 24) * SS + t];

        int accP[2][4][4], accQ[2][4][4], accR[2][4][4];
        #pragma unroll
        for (int a = 0; a < 2; a++)
            #pragma unroll
            for (int b = 0; b < 4; b++)
                #pragma unroll
                for (int c = 0; c < 4; c++) {
                    accP[a][b][c] = 0; accQ[a][b][c] = 0; accR[a][b][c] = 0;
                }

        // slice-local fill: this wm-slice's 32 A rows, both planes (512 x 16B, 64 thr)
        auto fillg = [&](int c) {
            const uint32_t stb = sb + A_BASE + (c % 3) * A_STAGE;
            const int k0 = c * 128;
            #pragma unroll
            for (int i = 0; i < 8; ++i) {
                int gg = li + i * 64;             // 0..511
                int plane = gg >> 8, r32 = (gg >> 3) & 31, c16 = gg & 7;
                int r = wm * 32 + r32;
                const signed char* a = plane ? ha2 : ha1;
                const char* src = (const char*)(a + (M0 + r) * HH + k0) + c16 * 16;
                uint32_t dst = stb + plane * A_PLANE + r * 128 +
                               (((uint32_t)(c16 ^ (r & 7))) << 4);
                CP_ASYNC16(dst, src);
            }
            CP_COMMIT();
        };

        if (t > 0) {   // t = 0: h is all-zero -> GEMM contributes exactly 0; skip it
            if (warp == wm && lane == 0) {
                const unsigned target = 8u * t;
                unsigned v;
                do {
                    asm volatile("ld.acquire.gpu.global.u32 %0, [%1];" : "=r"(v) : "l"(ctr_lo));
                } while (v < target);
            }
            GBAR64(1 + wm);
            fillg(0); fillg(1);
            if (warp == wm && lane == 0) {
                const unsigned target = 8u * t;
                unsigned v;
                do {
                    asm volatile("ld.acquire.gpu.global.u32 %0, [%1];" : "=r"(v) : "l"(ctr_hi));
                } while (v < target);
            }
            GBAR64(1 + wm);

            // fragment double-buffer
            uint32_t A1f[2][2][4], A2f[2][2][4];   // [buf][mi][4]
            uint32_t B1f[2][4][2], B2f[2][4][2];   // [buf][ni][2]

            auto load_frags = [&](int buf, uint32_t stb, int c, int ks) {
                const uint32_t acol = ((uint32_t)((ks * 2 + ka) ^ arx)) << 4;
                #pragma unroll
                for (int mi = 0; mi < 2; ++mi) {
                    uint32_t ad = stb + (a_row + mi * 16) * 128 + acol;
                    LDSM4(A1f[buf][mi][0], A1f[buf][mi][1], A1f[buf][mi][2], A1f[buf][mi][3], ad);
                    LDSM4(A2f[buf][mi][0], A2f[buf][mi][1], A2f[buf][mi][2], A2f[buf][mi][3], ad + A_PLANE);
                }
                {
                    uint32_t bd = bbase + c * 128 + (((uint32_t)((ks * 2 + kb) ^ brx)) << 4);
                    LDSM4(B1f[buf][0][0], B1f[buf][0][1], B1f[buf][1][0], B1f[buf][1][1], bd);
                    LDSM4(B2f[buf][0][0], B2f[buf][0][1], B2f[buf][1][0], B2f[buf][1][1], bd + B_PLANE);
                    uint32_t bd2 = bbase2 + c * 128 + (((uint32_t)((ks * 2 + kb) ^ brx2)) << 4);
                    LDSM4(B1f[buf][2][0], B1f[buf][2][1], B1f[buf][3][0], B1f[buf][3][1], bd2);
                    LDSM4(B2f[buf][2][0], B2f[buf][2][1], B2f[buf][3][0], B2f[buf][3][1], bd2 + B_PLANE);
                }
            };
            auto issue_mma = [&](int buf) {
                #pragma unroll
                for (int mi = 0; mi < 2; ++mi)
                    #pragma unroll
                    for (int ni = 0; ni < 4; ++ni) {
                        mma_s8(accP[mi][ni], A1f[buf][mi], B1f[buf][ni]);
                        mma_s8(accQ[mi][ni], A2f[buf][mi], B1f[buf][ni]);
                        mma_s8(accR[mi][ni], A1f[buf][mi], B2f[buf][ni]);
                    }
            };

            #pragma unroll
            for (int c = 0; c < 8; ++c) {
                if (c < 7) { CP_WAIT(1); } else { CP_WAIT(0); }
                GBAR64(1 + wm);               // slice convergence: chunk-c data landed
                if (c + 2 < 8) fillg(c + 2);

                const uint32_t stb = sb + A_BASE + (c % 3) * A_STAGE;
                load_frags(0, stb, c, 0);
                #pragma unroll
                for (int ks = 0; ks < 4; ++ks) {
                    if (ks < 3) load_frags((ks + 1) & 1, stb, c, ks + 1);
                    issue_mma(ks & 1);
                }
            }
        }

        // epilogue: v = accP*2^-18 + (accQ+accR)*2^-25 + x*whx + bh; tanh;
        // re-split to int8; STAGE packed u16s in SMEM, then coalesced STG.
        #pragma unroll
        for (int mi = 0; mi < 2; ++mi) {
            const int rr0 = gid + mi * 16;       // slice-relative rows rr0, rr0+8
            const float x0 = mi ? x10 : x00;
            const float x1 = mi ? x11 : x01;
            #pragma unroll
            for (int ni = 0; ni < 4; ++ni) {
                const int nc = wn * 32 + 2 * tig + ni * 8;   // col within 64
                const float w0 = whx_s[nc], w1 = whx_s[nc + 1];
                const float b0 = bh_s[nc],  b1 = bh_s[nc + 1];
                float v00 = fast_tanh((float)accP[mi][ni][0] * SC_P + (float)(accQ[mi][ni][0] + accR[mi][ni][0]) * SC_Q + x0 * w0 + b0);
                float v01 = fast_tanh((float)accP[mi][ni][1] * SC_P + (float)(accQ[mi][ni][1] + accR[mi][ni][1]) * SC_Q + x0 * w1 + b1);
                float v10 = fast_tanh((float)accP[mi][ni][2] * SC_P + (float)(accQ[mi][ni][2] + accR[mi][ni][2]) * SC_Q + x1 * w0 + b0);
                float v11 = fast_tanh((float)accP[mi][ni][3] * SC_P + (float)(accQ[mi][ni][3] + accR[mi][ni][3]) * SC_Q + x1 * w1 + b1);
                int p00 = clamp127(v00 * 128.f), p01 = clamp127(v01 * 128.f);
                int p10 = clamp127(v10 * 128.f), p11 = clamp127(v11 * 128.f);
                int q00 = clamp127((v00 - (float)p00 * 0.0078125f) * 16384.f);
                int q01 = clamp127((v01 - (float)p01 * 0.0078125f) * 16384.f);
                int q10 = clamp127((v10 - (float)p10 * 0.0078125f) * 16384.f);
                int q11 = clamp127((v11 - (float)p11 * 0.0078125f) * 16384.f);
                char* s0 = smem + stg_base + rr0 * 80 + nc;
                char* s1 = smem + stg_base + (rr0 + 8) * 80 + nc;
                *(uint16_t*)(s0)           = (uint16_t)((p00 & 0xFF) | ((p01 & 0xFF) << 8));
                *(uint16_t*)(s0 + A_PLANE) = (uint16_t)((q00 & 0xFF) | ((q01 & 0xFF) << 8));
                *(uint16_t*)(s1)           = (uint16_t)((p10 & 0xFF) | ((p11 & 0xFF) << 8));
                *(uint16_t*)(s1 + A_PLANE) = (uint16_t)((q10 & 0xFF) | ((q11 & 0xFF) << 8));
            }
        }
        GBAR64(1 + wm);

        // cooperative coalesced store: 64 threads x (one row-plane of 64B)
        {
            signed char* __restrict__ o1 = g_ha1[(t + 1) & 1];
            signed char* __restrict__ o2 = g_ha2[(t + 1) & 1];
            const int pl = li >> 5, rr = li & 31;
            const char* srow = smem + stg_base + pl * A_PLANE + rr * 80;
            signed char* drow = (pl ? o2 : o1) + (M0 + wm * 32 + rr) * HH + N0;
            uint4 d0 = *(const uint4*)(srow);
            uint4 d1 = *(const uint4*)(srow + 16);
            uint4 d2 = *(const uint4*)(srow + 32);
            uint4 d3 = *(const uint4*)(srow + 48);
            *(uint4*)(drow)      = d0;
            *(uint4*)(drow + 16) = d1;
            *(uint4*)(drow + 32) = d2;
            *(uint4*)(drow + 48) = d3;
        }

        // publish: slice stores visible (named bar), then release our half-counter
        if (t + 1 < SS) {
            GBAR64(1 + wm);
            if (warp == wm && lane == 0) {
                __threadfence();
                atomicAdd(ctr_pub, 1u);
            }
        }
    }
}

// ---------------- output projection (+ counter reset for graph replays) ----------------
__global__ void proj_kernel(const float* __restrict__ wph,
                            const float* __restrict__ bp,
                            float* __restrict__ out) {
    __shared__ float red[CC][128];
    int b = blockIdx.x, tid = threadIdx.x;
    if (b == 0) {
        for (int i = tid; i < 8 * 4 * 2 * 32; i += 128) g_barw[i] = 0u;
    }
    float acc[CC];
    #pragma unroll
    for (int c = 0; c < CC; ++c) acc[c] = 0.f;
    for (int k = tid; k < HH; k += 128) {
        float hv = (float)g_ha1[0][b * HH + k] * 0.0078125f
                 + (float)g_ha2[0][b * HH + k] * 6.103515625e-5f;
        #pragma unroll
        for (int c = 0; c < CC; ++c) acc[c] += hv * wph[c * HH + k];
    }
    #pragma unroll
    for (int c = 0; c < CC; ++c) red[c][tid] = acc[c];
    __syncthreads();
    for (int off = 64; off > 0; off >>= 1) {
        if (tid < off) {
            #pragma unroll
            for (int c = 0; c < CC; ++c) red[c][tid] += red[c][tid + off];
        }
        __syncthreads();
    }
    if (tid < CC) out[b * CC + tid] = red[tid][0] + bp[tid];
}

extern "C" void kernel_launch(void* const* d_in, const int* in_sizes, int n_in,
                              void* d_out, int out_size) {
    const float* x   = (const float*)d_in[0];
    const float* whx = (const float*)d_in[1];
    const float* whh = (const float*)d_in[2];
    const float* bh  = (const float*)d_in[3];
    const float* wph = (const float*)d_in[4];
    const float* bp  = (const float*)d_in[5];
    float* out = (float*)d_out;

    cudaFuncSetAttribute(rnn_persist,
                         cudaFuncAttributeMaxDynamicSharedMemorySize, SMEM_TOTAL);

    rnn_persist<<<NCTA, 256, SMEM_TOTAL>>>(x, whx, bh, whh);
    proj_kernel<<<BB, 128>>>(wph, bp, out);
}